// round 2
// baseline (speedup 1.0000x reference)
#include <cuda_runtime.h>
#include <cstdint>

#define NB 64
#define NN 1024
#define DD 128
#define KK 6

// Scratch: G[j][k][d] = F2[0,j,:] . Wnb[d, k*DD:(k+1)*DD]   (3 MB, L2-resident)
__device__ float g_G[NN * KK * DD];

// ---------------------------------------------------------------------------
// K1: compute F2 rows for batch 0 and project through Wnb into G.
// grid = 64 blocks (16 j-rows each), 768 threads (t -> k = t>>7, d = t&127).
// ---------------------------------------------------------------------------
__global__ void k_precompute(const float* __restrict__ loc,
                             const float* __restrict__ W2d,
                             const float* __restrict__ b2d,
                             const float* __restrict__ Wnb) {
    __shared__ float F2s[16][128];
    const int t = threadIdx.x;
    const int k = t >> 7, d = t & 127;
    const int j0 = blockIdx.x * 16;

    for (int idx = t; idx < 16 * 128; idx += 768) {
        int jr = idx >> 7, dd = idx & 127;
        int jg = j0 + jr;
        float x = loc[jg * 2 + 0], y = loc[jg * 2 + 1];
        F2s[jr][dd] = fmaf(y, W2d[dd * 2 + 1], fmaf(x, W2d[dd * 2 + 0], b2d[dd]));
    }
    __syncthreads();

    float acc[16];
#pragma unroll
    for (int jr = 0; jr < 16; jr++) acc[jr] = 0.f;

    const float* wrow = Wnb + d * (KK * DD) + k * DD;
#pragma unroll 4
    for (int dp = 0; dp < 128; dp++) {
        float w = __ldg(wrow + dp);
#pragma unroll
        for (int jr = 0; jr < 16; jr++) acc[jr] = fmaf(F2s[jr][dp], w, acc[jr]);
    }
#pragma unroll
    for (int jr = 0; jr < 16; jr++)
        g_G[((j0 + jr) * KK + k) * DD + d] = acc[jr];
}

// ---------------------------------------------------------------------------
// K2: per batch: brute-force kNN (K=6, stable lower-index-first tie-break),
// then gather G rows + bnb + F3 + leaky-relu, write h[b, n+1, :].
// grid = 256 blocks (4 per batch, 256 rows each), 256 threads.
// Phase 1: one thread per row; Phase 2: one warp per row (coalesced float4).
// ---------------------------------------------------------------------------
__global__ void k_nbr_gather(const float* __restrict__ loc,
                             const float* __restrict__ deadline,
                             const float* __restrict__ W3d,
                             const float* __restrict__ b3d,
                             const float* __restrict__ bnb,
                             float* __restrict__ h) {
    __shared__ float2 locs[NN];
    __shared__ int nbr[256][KK];

    const int b = blockIdx.x >> 2;
    const int rowbase = (blockIdx.x & 3) << 8;
    const int tid = threadIdx.x;

    const float2* locb = (const float2*)(loc + (size_t)b * NN * 2);
    for (int idx = tid; idx < NN; idx += 256) locs[idx] = locb[idx];
    __syncthreads();

    // ---- Phase 1: top-6 nearest (squared distance, stable ties) ----
    {
        const int n = rowbase + tid;
        const float xi = locs[n].x, yi = locs[n].y;
        const float INF = __int_as_float(0x7f800000);
        float bd[KK];
        int bi[KK];
#pragma unroll
        for (int m = 0; m < KK; m++) { bd[m] = INF; bi[m] = 0; }

        for (int j = 0; j < NN; j++) {
            float dx = locs[j].x - xi;
            float dy = locs[j].y - yi;
            float d2 = fmaf(dx, dx, dy * dy);
            if (d2 < bd[KK - 1]) {          // strict < : equal keeps earlier index
                int p = KK - 1;
#pragma unroll
                for (int m = KK - 1; m >= 1; --m) {
                    if (d2 < bd[m - 1]) { bd[m] = bd[m - 1]; bi[m] = bi[m - 1]; p = m - 1; }
                }
                bd[p] = d2; bi[p] = j;
            }
        }
#pragma unroll
        for (int m = 0; m < KK; m++) nbr[tid][m] = bi[m];
    }
    __syncthreads();

    // ---- Phase 2: warp-per-row gather + F3 + leaky ----
    const int w = tid >> 5, l = tid & 31;   // lane l owns d = 4l..4l+3
    float w3[4][3], b3v[4];
#pragma unroll
    for (int q = 0; q < 4; q++) {
        int d = 4 * l + q;
        w3[q][0] = W3d[d * 3 + 0];
        w3[q][1] = W3d[d * 3 + 1];
        w3[q][2] = W3d[d * 3 + 2];
        b3v[q] = b3d[d];
    }
    float4 bnv = ((const float4*)bnb)[l];

    for (int r = w; r < 256; r += 8) {
        const int n = rowbase + r;
        float a[4] = {bnv.x, bnv.y, bnv.z, bnv.w};
#pragma unroll
        for (int k = 0; k < KK; k++) {
            int j = nbr[r][k];
            float4 g = ((const float4*)(g_G + (size_t)(j * KK + k) * DD))[l];
            a[0] += g.x; a[1] += g.y; a[2] += g.z; a[3] += g.w;
        }
        float xn = locs[n].x, yn = locs[n].y;
        float tn = deadline[(size_t)b * NN + n];

        float4 o;
        float* op = (float*)&o;
#pragma unroll
        for (int q = 0; q < 4; q++) {
            float f3 = fmaf(tn, w3[q][2], fmaf(yn, w3[q][1], fmaf(xn, w3[q][0], b3v[q])));
            float v = a[q] + f3;
            op[q] = (v >= 0.f) ? v : 0.01f * v;
        }
        ((float4*)(h + ((size_t)(b * (NN + 1) + n + 1)) * DD))[l] = o;
    }
}

// ---------------------------------------------------------------------------
// K3: depot row (h[b,0,:]) + mean over axis 1 (1025 rows).
// grid = 64 (batch), 1024 threads: d = tid&127, group g = tid>>7 sums 128 rows.
// ---------------------------------------------------------------------------
__global__ void k_mean_dep(const float* __restrict__ depot,
                           const float* __restrict__ Wdep,
                           const float* __restrict__ bdep,
                           float* __restrict__ h,
                           float* __restrict__ mean_out) {
    __shared__ float part[8][128];
    const int b = blockIdx.x;
    const int tid = threadIdx.x;
    const int d = tid & 127, g = tid >> 7;

    float* hb = h + (size_t)b * (NN + 1) * DD;
    float s = 0.f;
    if (g == 0) {
        float dep = fmaf(depot[b * 2 + 1], Wdep[d * 2 + 1],
                         fmaf(depot[b * 2 + 0], Wdep[d * 2 + 0], bdep[d]));
        dep = (dep >= 0.f) ? dep : 0.01f * dep;
        hb[d] = dep;
        s = dep;
    }
    const int i0 = 1 + g * 128, i1 = i0 + 128;
#pragma unroll 4
    for (int i = i0; i < i1; i++) s += hb[(size_t)i * DD + d];
    part[g][d] = s;
    __syncthreads();
    if (g == 0) {
        float t = 0.f;
#pragma unroll
        for (int q = 0; q < 8; q++) t += part[q][d];
        mean_out[b * DD + d] = t / 1025.0f;
    }
}

// ---------------------------------------------------------------------------
extern "C" void kernel_launch(void* const* d_in, const int* in_sizes, int n_in,
                              void* d_out, int out_size) {
    const float* loc      = (const float*)d_in[0];
    const float* deadline = (const float*)d_in[1];
    const float* depot    = (const float*)d_in[2];
    const float* W3d      = (const float*)d_in[3];
    const float* b3d      = (const float*)d_in[4];
    const float* W2d      = (const float*)d_in[5];
    const float* b2d      = (const float*)d_in[6];
    const float* Wnb      = (const float*)d_in[7];
    const float* bnb      = (const float*)d_in[8];
    const float* Wdep     = (const float*)d_in[9];
    const float* bdep     = (const float*)d_in[10];

    float* h = (float*)d_out;
    float* mean_out = h + (size_t)NB * (NN + 1) * DD;

    k_precompute<<<NN / 16, 768>>>(loc, W2d, b2d, Wnb);
    k_nbr_gather<<<NB * 4, 256>>>(loc, deadline, W3d, b3d, bnb, h);
    k_mean_dep<<<NB, 1024>>>(depot, Wdep, bdep, h, mean_out);
}

// round 3
// speedup vs baseline: 1.3150x; 1.3150x over previous
#include <cuda_runtime.h>
#include <cstdint>

#define NB 64
#define NN 1024
#define DD 128
#define KK 6

// Scratch: G[j][k][d] = F2[0,j,:] . Wnb[d, k*DD:(k+1)*DD]   (3 MB, L2-resident)
__device__ float g_G[NN * KK * DD];

// ---------------------------------------------------------------------------
// K1: tiled GEMM  G[j, k, d] = sum_dp F2[0,j,dp] * Wnb[d, k*128+dp]
// grid = 32 j-tiles * 6 k = 192 blocks, 256 threads.
// Each block: 32 j x 128 d for one k. Thread computes 4j x 4d register tile.
// Wnb staged coalesced into shared, transposed with pad-129 (conflict-free).
// ---------------------------------------------------------------------------
__global__ void k_precompute(const float* __restrict__ loc,
                             const float* __restrict__ W2d,
                             const float* __restrict__ b2d,
                             const float* __restrict__ Wnb) {
    __shared__ float F2s[32][128];
    __shared__ float Ws[32][129];

    const int bx = blockIdx.x;
    const int jt = bx / KK;
    const int k  = bx - jt * KK;
    const int j0 = jt * 32;
    const int tid = threadIdx.x;

    // Stage F2 rows j0..j0+31 (batch 0).
    for (int idx = tid; idx < 32 * 128; idx += 256) {
        int jr = idx >> 7, dd = idx & 127;
        int jg = j0 + jr;
        float x = loc[jg * 2 + 0], y = loc[jg * 2 + 1];
        F2s[jr][dd] = fmaf(y, W2d[dd * 2 + 1], fmaf(x, W2d[dd * 2 + 0], b2d[dd]));
    }

    const int tj = tid >> 5;      // 0..7  -> j sub-tile of 4
    const int td = tid & 31;      // 0..31 -> d = td + 32*q
    const int ld_dp = tid & 31;   // staging: lane -> dp (coalesced global read)
    const int ld_d0 = tid >> 5;   // staging: warp  -> d

    float acc[4][4] = {};

    for (int dpc = 0; dpc < 128; dpc += 32) {
        __syncthreads();   // first iter: covers F2s; later: protects Ws reuse
        // Ws[dp][d] = Wnb[d*768 + k*128 + dpc + dp]; lanes read consecutive dp.
        for (int dd = ld_d0; dd < 128; dd += 8)
            Ws[ld_dp][dd] = Wnb[dd * (KK * DD) + k * DD + dpc + ld_dp];
        __syncthreads();

#pragma unroll 8
        for (int dp = 0; dp < 32; dp++) {
            float w0 = Ws[dp][td];
            float w1 = Ws[dp][td + 32];
            float w2 = Ws[dp][td + 64];
            float w3 = Ws[dp][td + 96];
#pragma unroll
            for (int jj = 0; jj < 4; jj++) {
                float f = F2s[tj * 4 + jj][dpc + dp];   // broadcast
                acc[jj][0] = fmaf(f, w0, acc[jj][0]);
                acc[jj][1] = fmaf(f, w1, acc[jj][1]);
                acc[jj][2] = fmaf(f, w2, acc[jj][2]);
                acc[jj][3] = fmaf(f, w3, acc[jj][3]);
            }
        }
    }

#pragma unroll
    for (int jj = 0; jj < 4; jj++) {
        int j = j0 + tj * 4 + jj;
#pragma unroll
        for (int q = 0; q < 4; q++)
            g_G[((size_t)(j * KK + k)) * DD + td + 32 * q] = acc[jj][q];
    }
}

// ---------------------------------------------------------------------------
// K2: per batch: brute-force kNN (K=6, stable lower-index-first tie-break),
// then gather G rows + bnb + F3 + leaky-relu, write h[b, n+1, :].
// grid = 256 blocks (4 per batch, 256 rows each), 256 threads.
// ---------------------------------------------------------------------------
__global__ void k_nbr_gather(const float* __restrict__ loc,
                             const float* __restrict__ deadline,
                             const float* __restrict__ W3d,
                             const float* __restrict__ b3d,
                             const float* __restrict__ bnb,
                             float* __restrict__ h) {
    __shared__ float2 locs[NN];
    __shared__ int nbr[256][KK];

    const int b = blockIdx.x >> 2;
    const int rowbase = (blockIdx.x & 3) << 8;
    const int tid = threadIdx.x;

    const float2* locb = (const float2*)(loc + (size_t)b * NN * 2);
    for (int idx = tid; idx < NN; idx += 256) locs[idx] = locb[idx];
    __syncthreads();

    // ---- Phase 1: top-6 nearest (squared distance, stable ties) ----
    {
        const int n = rowbase + tid;
        const float xi = locs[n].x, yi = locs[n].y;
        const float INF = __int_as_float(0x7f800000);
        float bd[KK];
        int bi[KK];
#pragma unroll
        for (int m = 0; m < KK; m++) { bd[m] = INF; bi[m] = 0; }

#pragma unroll 4
        for (int j = 0; j < NN; j++) {
            float dx = locs[j].x - xi;
            float dy = locs[j].y - yi;
            float d2 = fmaf(dx, dx, dy * dy);
            if (d2 < bd[KK - 1]) {          // strict < : equal keeps earlier index
                int p = KK - 1;
#pragma unroll
                for (int m = KK - 1; m >= 1; --m) {
                    if (d2 < bd[m - 1]) { bd[m] = bd[m - 1]; bi[m] = bi[m - 1]; p = m - 1; }
                }
                bd[p] = d2; bi[p] = j;
            }
        }
#pragma unroll
        for (int m = 0; m < KK; m++) nbr[tid][m] = bi[m];
    }
    __syncthreads();

    // ---- Phase 2: warp-per-row gather + F3 + leaky ----
    const int w = tid >> 5, l = tid & 31;   // lane l owns d = 4l..4l+3
    float w3[4][3], b3v[4];
#pragma unroll
    for (int q = 0; q < 4; q++) {
        int d = 4 * l + q;
        w3[q][0] = W3d[d * 3 + 0];
        w3[q][1] = W3d[d * 3 + 1];
        w3[q][2] = W3d[d * 3 + 2];
        b3v[q] = b3d[d];
    }
    float4 bnv = ((const float4*)bnb)[l];

    for (int r = w; r < 256; r += 8) {
        const int n = rowbase + r;
        float a[4] = {bnv.x, bnv.y, bnv.z, bnv.w};
#pragma unroll
        for (int k = 0; k < KK; k++) {
            int j = nbr[r][k];
            float4 g = ((const float4*)(g_G + (size_t)(j * KK + k) * DD))[l];
            a[0] += g.x; a[1] += g.y; a[2] += g.z; a[3] += g.w;
        }
        float xn = locs[n].x, yn = locs[n].y;
        float tn = deadline[(size_t)b * NN + n];

        float4 o;
        float* op = (float*)&o;
#pragma unroll
        for (int q = 0; q < 4; q++) {
            float f3 = fmaf(tn, w3[q][2], fmaf(yn, w3[q][1], fmaf(xn, w3[q][0], b3v[q])));
            float v = a[q] + f3;
            op[q] = (v >= 0.f) ? v : 0.01f * v;
        }
        ((float4*)(h + ((size_t)(b * (NN + 1) + n + 1)) * DD))[l] = o;
    }
}

// ---------------------------------------------------------------------------
// K3: depot row (h[b,0,:]) + mean over axis 1 (1025 rows).
// grid = 64 (batch), 1024 threads: d = tid&127, group g = tid>>7 sums 128 rows.
// ---------------------------------------------------------------------------
__global__ void k_mean_dep(const float* __restrict__ depot,
                           const float* __restrict__ Wdep,
                           const float* __restrict__ bdep,
                           float* __restrict__ h,
                           float* __restrict__ mean_out) {
    __shared__ float part[8][128];
    const int b = blockIdx.x;
    const int tid = threadIdx.x;
    const int d = tid & 127, g = tid >> 7;

    float* hb = h + (size_t)b * (NN + 1) * DD;
    float s = 0.f;
    if (g == 0) {
        float dep = fmaf(depot[b * 2 + 1], Wdep[d * 2 + 1],
                         fmaf(depot[b * 2 + 0], Wdep[d * 2 + 0], bdep[d]));
        dep = (dep >= 0.f) ? dep : 0.01f * dep;
        hb[d] = dep;
        s = dep;
    }
    const int i0 = 1 + g * 128, i1 = i0 + 128;
#pragma unroll 4
    for (int i = i0; i < i1; i++) s += hb[(size_t)i * DD + d];
    part[g][d] = s;
    __syncthreads();
    if (g == 0) {
        float t = 0.f;
#pragma unroll
        for (int q = 0; q < 8; q++) t += part[q][d];
        mean_out[b * DD + d] = t / 1025.0f;
    }
}

// ---------------------------------------------------------------------------
extern "C" void kernel_launch(void* const* d_in, const int* in_sizes, int n_in,
                              void* d_out, int out_size) {
    const float* loc      = (const float*)d_in[0];
    const float* deadline = (const float*)d_in[1];
    const float* depot    = (const float*)d_in[2];
    const float* W3d      = (const float*)d_in[3];
    const float* b3d      = (const float*)d_in[4];
    const float* W2d      = (const float*)d_in[5];
    const float* b2d      = (const float*)d_in[6];
    const float* Wnb      = (const float*)d_in[7];
    const float* bnb      = (const float*)d_in[8];
    const float* Wdep     = (const float*)d_in[9];
    const float* bdep     = (const float*)d_in[10];

    float* h = (float*)d_out;
    float* mean_out = h + (size_t)NB * (NN + 1) * DD;

    k_precompute<<<32 * KK, 256>>>(loc, W2d, b2d, Wnb);
    k_nbr_gather<<<NB * 4, 256>>>(loc, deadline, W3d, b3d, bnb, h);
    k_mean_dep<<<NB, 1024>>>(depot, Wdep, bdep, h, mean_out);
}

// round 5
// speedup vs baseline: 2.0660x; 1.5711x over previous
#include <cuda_runtime.h>
#include <cstdint>

#define NB 64
#define NN 1024
#define DD 128
#define KK 6
#define NBINS 64
#define BINW (1.0f / 64.0f)

// Scratch (device globals: no allocation allowed)
__device__ float g_G[NN * KK * DD];            // 3 MB  : G[j][k][d]
__device__ int   g_nbr[NB * NN * KK];          // 1.5 MB: neighbor indices
__device__ float g_part[(NB * NN / 8) * DD];   // 4 MB  : per-gather-block mean partials

// ---------------------------------------------------------------------------
// K1: G[j,k,d] = sum_dp F2[0,j,dp] * Wnb[d, k*128+dp]
// grid = 32 j-tiles * 6 k = 192 blocks, 1024 threads. Thread tile 2j x 2d.
// ---------------------------------------------------------------------------
__global__ void k_precompute(const float* __restrict__ loc,
                             const float* __restrict__ W2d,
                             const float* __restrict__ b2d,
                             const float* __restrict__ Wnb) {
    __shared__ float F2s[32][128];
    __shared__ float Ws[32][129];

    const int bx = blockIdx.x;
    const int jt = bx / KK;
    const int k  = bx - jt * KK;
    const int j0 = jt * 32;
    const int tid = threadIdx.x;

    // Stage F2 rows j0..j0+31 (batch 0): 4096 entries / 1024 threads.
    for (int idx = tid; idx < 32 * 128; idx += 1024) {
        int jr = idx >> 7, dd = idx & 127;
        int jg = j0 + jr;
        float x = loc[jg * 2 + 0], y = loc[jg * 2 + 1];
        F2s[jr][dd] = fmaf(y, W2d[dd * 2 + 1], fmaf(x, W2d[dd * 2 + 0], b2d[dd]));
    }

    const int td = tid & 63;      // d and d+64
    const int tj = tid >> 6;      // 0..15 -> rows 2tj, 2tj+1
    const int ldp = tid & 31;     // staging lane -> dp (coalesced)
    const int ld0 = tid >> 5;     // staging warp  -> d

    float a00 = 0.f, a01 = 0.f, a10 = 0.f, a11 = 0.f;

    for (int dpc = 0; dpc < 128; dpc += 32) {
        __syncthreads();
        for (int dd = ld0; dd < 128; dd += 32)
            Ws[ldp][dd] = Wnb[dd * (KK * DD) + k * DD + dpc + ldp];
        __syncthreads();

#pragma unroll
        for (int dp = 0; dp < 32; dp++) {
            float w0 = Ws[dp][td];
            float w1 = Ws[dp][td + 64];
            float f0 = F2s[2 * tj + 0][dpc + dp];
            float f1 = F2s[2 * tj + 1][dpc + dp];
            a00 = fmaf(f0, w0, a00);
            a01 = fmaf(f0, w1, a01);
            a10 = fmaf(f1, w0, a10);
            a11 = fmaf(f1, w1, a11);
        }
    }

    {
        size_t r0 = ((size_t)((j0 + 2 * tj + 0) * KK + k)) * DD;
        size_t r1 = ((size_t)((j0 + 2 * tj + 1) * KK + k)) * DD;
        g_G[r0 + td] = a00;  g_G[r0 + td + 64] = a01;
        g_G[r1 + td] = a10;  g_G[r1 + td + 64] = a11;
    }
}

// ---------------------------------------------------------------------------
// K2a: exact kNN via x-slab binning.
// grid = 256 (4 per batch), 256 threads (1 row/thread).
// Selection key = (d2_bits << 32) | j  -> lexicographic (d2, lower-j) order,
// independent of scan order. Pruning: skip bin iff dxmin^2 > current bd5.
// ---------------------------------------------------------------------------
__global__ void k_knn(const float* __restrict__ loc) {
    __shared__ float2 lx[NN];              // original-order points
    __shared__ float2 ps[NN];              // bin-sorted points
    __shared__ short  js[NN];              // bin-sorted original indices
    __shared__ unsigned char binOf[NN];
    __shared__ int bin_cnt[NBINS];
    __shared__ int bin_start[NBINS];
    __shared__ int bin_fill[NBINS];

    const int b = blockIdx.x >> 2;
    const int rowbase = (blockIdx.x & 3) << 8;
    const int tid = threadIdx.x;

    if (tid < NBINS) { bin_cnt[tid] = 0; bin_fill[tid] = 0; }
    __syncthreads();

    const float2* locb = (const float2*)(loc + (size_t)b * NN * 2);
    for (int j = tid; j < NN; j += 256) {
        float2 p = locb[j];
        lx[j] = p;
        int bn = (int)(p.x * 64.0f);
        bn = bn < 0 ? 0 : (bn > 63 ? 63 : bn);
        binOf[j] = (unsigned char)bn;
        atomicAdd(&bin_cnt[bn], 1);
    }
    __syncthreads();

    // Exclusive prefix over 64 bins by warp 0.
    if (tid < 32) {
        int c0 = bin_cnt[tid];
        int c1 = bin_cnt[tid + 32];
        int s0 = c0, s1 = c1;
#pragma unroll
        for (int off = 1; off < 32; off <<= 1) {
            int v0 = __shfl_up_sync(0xffffffffu, s0, off);
            int v1 = __shfl_up_sync(0xffffffffu, s1, off);
            if (tid >= off) { s0 += v0; s1 += v1; }
        }
        int tot0 = __shfl_sync(0xffffffffu, s0, 31);
        bin_start[tid]      = s0 - c0;
        bin_start[tid + 32] = s1 + tot0 - c1;
    }
    __syncthreads();

    // Deterministic scatter by warp 0: j-order ranks within each bin.
    // Group leader reserves the group's slot range atomically and broadcasts;
    // final layout is j-ascending within each bin regardless of atomic order
    // (groups of the same bin never coexist in one iteration; g-loop serial).
    if (tid < 32) {
        const unsigned lmask = (1u << tid) - 1u;
        for (int g = 0; g < 32; g++) {
            int j = g * 32 + tid;
            int bn = binOf[j];
            unsigned mask = __match_any_sync(0xffffffffu, bn);
            int leader = __ffs(mask) - 1;
            int lower = __popc(mask & lmask);
            int base = 0;
            if (tid == leader) base = atomicAdd(&bin_fill[bn], __popc(mask));
            base = __shfl_sync(0xffffffffu, base, leader);
            int pos = bin_start[bn] + base + lower;
            ps[pos] = lx[j];
            js[pos] = (short)j;
        }
    }
    __syncthreads();

    // Per-row outward scan.
    const int n = rowbase + tid;
    const float xi = lx[n].x, yi = lx[n].y;
    const unsigned long long KINIT =
        (((unsigned long long)0x7f800000u) << 32) | 0xffffffffull;
    unsigned long long k0 = KINIT, k1 = KINIT, k2 = KINIT,
                       k3 = KINIT, k4 = KINIT, k5 = KINIT;

#define PROC_BIN(c)                                                          \
    {                                                                        \
        int s_ = bin_start[c];                                               \
        int e_ = s_ + bin_cnt[c];                                            \
        for (int i_ = s_; i_ < e_; i_++) {                                   \
            float2 p_ = ps[i_];                                              \
            float dx_ = p_.x - xi;                                           \
            float dy_ = p_.y - yi;                                           \
            float d2_ = fmaf(dx_, dx_, dy_ * dy_);                           \
            unsigned long long key_ =                                        \
                (((unsigned long long)__float_as_uint(d2_)) << 32) |         \
                (unsigned)(unsigned short)js[i_];                            \
            if (key_ < k5) {                                                 \
                bool c4 = key_ < k4, c3 = key_ < k3, c2 = key_ < k2,         \
                     c1_ = key_ < k1, c0_ = key_ < k0;                       \
                k5 = c4 ? k4 : key_;                                         \
                k4 = c4 ? (c3 ? k3 : key_) : k4;                             \
                k3 = c3 ? (c2 ? k2 : key_) : k3;                             \
                k2 = c2 ? (c1_ ? k1 : key_) : k2;                            \
                k1 = c1_ ? (c0_ ? k0 : key_) : k1;                           \
                k0 = c0_ ? key_ : k0;                                        \
            }                                                                \
        }                                                                    \
    }

    int b0 = (int)(xi * 64.0f);
    b0 = b0 < 0 ? 0 : (b0 > 63 ? 63 : b0);
    PROC_BIN(b0);
    int cr = b0 + 1, cl = b0 - 1;
    bool rA = cr < NBINS, lA = cl >= 0;
    while (rA || lA) {
        if (rA) {
            float t = __uint_as_float((unsigned)(k5 >> 32));
            float dmin = cr * BINW - xi;
            if (dmin * dmin > t) rA = false;
            else { PROC_BIN(cr); cr++; rA = cr < NBINS; }
        }
        if (lA) {
            float t = __uint_as_float((unsigned)(k5 >> 32));
            float dmin = xi - (cl + 1) * BINW;
            if (dmin * dmin > t) lA = false;
            else { PROC_BIN(cl); cl--; lA = cl >= 0; }
        }
    }
#undef PROC_BIN

    int obase = (b * NN + n) * KK;
    g_nbr[obase + 0] = (int)(k0 & 0xffffffffu);
    g_nbr[obase + 1] = (int)(k1 & 0xffffffffu);
    g_nbr[obase + 2] = (int)(k2 & 0xffffffffu);
    g_nbr[obase + 3] = (int)(k3 & 0xffffffffu);
    g_nbr[obase + 4] = (int)(k4 & 0xffffffffu);
    g_nbr[obase + 5] = (int)(k5 & 0xffffffffu);
}

// ---------------------------------------------------------------------------
// K2b: gather G rows + bnb + F3 + leaky-relu; write h[b,n+1,:]; block-level
// mean partial (deterministic smem reduce) to g_part.
// grid = 8192 blocks (8 rows each, 1 warp/row), 256 threads.
// ---------------------------------------------------------------------------
__global__ void k_gather(const float* __restrict__ loc,
                         const float* __restrict__ deadline,
                         const float* __restrict__ W3d,
                         const float* __restrict__ b3d,
                         const float* __restrict__ bnb,
                         float* __restrict__ h) {
    __shared__ float red[8][128];
    const int tid = threadIdx.x;
    const int w = tid >> 5, l = tid & 31;
    const int row = blockIdx.x * 8 + w;          // 0..65535
    const int b = row >> 10, n = row & 1023;

    float w3[4][3], b3v[4];
#pragma unroll
    for (int q = 0; q < 4; q++) {
        int d = 4 * l + q;
        w3[q][0] = W3d[d * 3 + 0];
        w3[q][1] = W3d[d * 3 + 1];
        w3[q][2] = W3d[d * 3 + 2];
        b3v[q] = b3d[d];
    }
    float4 bnv = ((const float4*)bnb)[l];
    float a[4] = {bnv.x, bnv.y, bnv.z, bnv.w};

    const int* nb = g_nbr + (size_t)row * KK;
#pragma unroll
    for (int k = 0; k < KK; k++) {
        int j = __ldg(nb + k);
        float4 g = ((const float4*)(g_G + (size_t)(j * KK + k) * DD))[l];
        a[0] += g.x; a[1] += g.y; a[2] += g.z; a[3] += g.w;
    }

    float xn = loc[(size_t)row * 2 + 0];
    float yn = loc[(size_t)row * 2 + 1];
    float tn = deadline[row];

    float4 o;
    float* op = (float*)&o;
#pragma unroll
    for (int q = 0; q < 4; q++) {
        float f3 = fmaf(tn, w3[q][2], fmaf(yn, w3[q][1], fmaf(xn, w3[q][0], b3v[q])));
        float v = a[q] + f3;
        op[q] = (v >= 0.f) ? v : 0.01f * v;
    }
    ((float4*)(h + ((size_t)(b * (NN + 1) + n + 1)) * DD))[l] = o;

    // Mean partial over this block's 8 rows (deterministic order).
    ((float4*)red[w])[l] = o;
    __syncthreads();
    if (tid < 128) {
        float s = 0.f;
#pragma unroll
        for (int q = 0; q < 8; q++) s += red[q][tid];
        g_part[(size_t)blockIdx.x * DD + tid] = s;
    }
}

// ---------------------------------------------------------------------------
// K3: depot row + final mean combine. grid = 64, 128 threads.
// ---------------------------------------------------------------------------
__global__ void k_final(const float* __restrict__ depot,
                        const float* __restrict__ Wdep,
                        const float* __restrict__ bdep,
                        float* __restrict__ h,
                        float* __restrict__ mean_out) {
    const int b = blockIdx.x;
    const int d = threadIdx.x;

    float dep = fmaf(depot[b * 2 + 1], Wdep[d * 2 + 1],
                     fmaf(depot[b * 2 + 0], Wdep[d * 2 + 0], bdep[d]));
    dep = (dep >= 0.f) ? dep : 0.01f * dep;
    h[(size_t)b * (NN + 1) * DD + d] = dep;

    float s = dep;
    const float* pp = g_part + (size_t)b * 128 * DD;
#pragma unroll 8
    for (int blk = 0; blk < 128; blk++) s += pp[blk * DD + d];
    mean_out[b * DD + d] = s / 1025.0f;
}

// ---------------------------------------------------------------------------
extern "C" void kernel_launch(void* const* d_in, const int* in_sizes, int n_in,
                              void* d_out, int out_size) {
    const float* loc      = (const float*)d_in[0];
    const float* deadline = (const float*)d_in[1];
    const float* depot    = (const float*)d_in[2];
    const float* W3d      = (const float*)d_in[3];
    const float* b3d      = (const float*)d_in[4];
    const float* W2d      = (const float*)d_in[5];
    const float* b2d      = (const float*)d_in[6];
    const float* Wnb      = (const float*)d_in[7];
    const float* bnb      = (const float*)d_in[8];
    const float* Wdep     = (const float*)d_in[9];
    const float* bdep     = (const float*)d_in[10];

    float* h = (float*)d_out;
    float* mean_out = h + (size_t)NB * (NN + 1) * DD;

    k_precompute<<<32 * KK, 1024>>>(loc, W2d, b2d, Wnb);
    k_knn<<<NB * 4, 256>>>(loc);
    k_gather<<<NB * NN / 8, 256>>>(loc, deadline, W3d, b3d, bnb, h);
    k_final<<<NB, 128>>>(depot, Wdep, bdep, h, mean_out);
}